// round 1
// baseline (speedup 1.0000x reference)
#include <cuda_runtime.h>
#include <math.h>

#define EMBED  1024
#define HEADS  16
#define HDIM   64
#define NBATCH 4
#define SEQ    2048

// ---- scratch (static __device__ globals; no allocation) ----
__device__ float g_q[(size_t)NBATCH * SEQ * EMBED];
__device__ float g_k[(size_t)NBATCH * SEQ * EMBED];
__device__ float g_v[(size_t)NBATCH * SEQ * EMBED];
__device__ float g_attn[(size_t)NBATCH * SEQ * EMBED];

// ============================================================
// Kernel 1: per-head-dim projections  out[r][e] = sum_d x[r][d] * W[e][d]
// rows r = flattened (n,l,h), 131072 rows of dim 64.
// grid: (4096, 3)  block: 256.  blockIdx.y selects q/k/v.
// ============================================================
__global__ void proj_kernel(const float* __restrict__ xq,
                            const float* __restrict__ xk,
                            const float* __restrict__ xv,
                            const float* __restrict__ Wq,
                            const float* __restrict__ Wk,
                            const float* __restrict__ Wv) {
    __shared__ float sW[64][68];
    __shared__ float sX[32][68];

    const float* x;
    const float* W;
    float* o;
    switch (blockIdx.y) {
        case 0:  x = xq; W = Wq; o = g_q; break;
        case 1:  x = xk; W = Wk; o = g_k; break;
        default: x = xv; W = Wv; o = g_v; break;
    }

    const int t = threadIdx.x;
    const int row0 = blockIdx.x * 32;

    // load W [64][64] (float4)
    #pragma unroll
    for (int i = t; i < 1024; i += 256) {
        int e = i >> 4;
        int d = (i & 15) * 4;
        *(float4*)&sW[e][d] = *(const float4*)&W[e * 64 + d];
    }
    // load 32 input rows (float4)
    #pragma unroll
    for (int i = t; i < 512; i += 256) {
        int r = i >> 4;
        int d = (i & 15) * 4;
        *(float4*)&sX[r][d] = *(const float4*)&x[(size_t)(row0 + r) * 64 + d];
    }
    __syncthreads();

    // each thread computes 8 outputs
    #pragma unroll
    for (int j = 0; j < 8; j++) {
        int idx = t + j * 256;     // 0..2047
        int r = idx >> 6;
        int e = idx & 63;
        float acc = 0.f;
        #pragma unroll
        for (int d = 0; d < 64; d += 4) {
            float4 xx = *(const float4*)&sX[r][d];
            float4 ww = *(const float4*)&sW[e][d];
            acc = fmaf(xx.x, ww.x, acc);
            acc = fmaf(xx.y, ww.y, acc);
            acc = fmaf(xx.z, ww.z, acc);
            acc = fmaf(xx.w, ww.w, acc);
        }
        o[(size_t)(row0 + r) * 64 + e] = acc;
    }
}

// ============================================================
// Kernel 2: flash attention, fp32, one Q row per thread.
// grid: (SEQ/128, HEADS, NBATCH)  block: 128
// scale 1/sqrt(EMBED)=1/32 folded into q.
// ============================================================
__global__ __launch_bounds__(128, 1)
void attn_kernel() {
    __shared__ float sK[64][68];
    __shared__ float sV[64][68];

    const int n = blockIdx.z;
    const int h = blockIdx.y;
    const int t = threadIdx.x;
    const int qrow = blockIdx.x * 128 + t;
    const size_t hb = (size_t)n * SEQ * EMBED + (size_t)h * HDIM;

    float qv[64];
    {
        const float* qp = g_q + hb + (size_t)qrow * EMBED;
        #pragma unroll
        for (int d = 0; d < 64; d += 4) {
            float4 v4 = *(const float4*)(qp + d);
            qv[d + 0] = v4.x * 0.03125f;
            qv[d + 1] = v4.y * 0.03125f;
            qv[d + 2] = v4.z * 0.03125f;
            qv[d + 3] = v4.w * 0.03125f;
        }
    }
    float o[64];
    #pragma unroll
    for (int d = 0; d < 64; d++) o[d] = 0.f;
    float mrun = -1e30f, lsum = 0.f;

    for (int kt = 0; kt < SEQ / 64; kt++) {
        __syncthreads();
        const float* kp = g_k + hb + (size_t)(kt * 64) * EMBED;
        const float* vp = g_v + hb + (size_t)(kt * 64) * EMBED;
        #pragma unroll
        for (int i = 0; i < 8; i++) {
            int f = t + i * 128;          // 0..1023 float4 slots
            int r = f >> 4;
            int d = (f & 15) * 4;
            *(float4*)&sK[r][d] = *(const float4*)(kp + (size_t)r * EMBED + d);
            *(float4*)&sV[r][d] = *(const float4*)(vp + (size_t)r * EMBED + d);
        }
        __syncthreads();

        #pragma unroll
        for (int c = 0; c < 4; c++) {
            float p[16];
            float mloc = mrun;
            #pragma unroll
            for (int jj = 0; jj < 16; jj++) {
                const float* kr = &sK[c * 16 + jj][0];
                float s0 = 0.f, s1 = 0.f;
                #pragma unroll
                for (int d = 0; d < 64; d += 8) {
                    float4 k0 = *(const float4*)(kr + d);
                    float4 k1 = *(const float4*)(kr + d + 4);
                    s0 = fmaf(qv[d + 0], k0.x, s0);
                    s1 = fmaf(qv[d + 1], k0.y, s1);
                    s0 = fmaf(qv[d + 2], k0.z, s0);
                    s1 = fmaf(qv[d + 3], k0.w, s1);
                    s0 = fmaf(qv[d + 4], k1.x, s0);
                    s1 = fmaf(qv[d + 5], k1.y, s1);
                    s0 = fmaf(qv[d + 6], k1.z, s0);
                    s1 = fmaf(qv[d + 7], k1.w, s1);
                }
                p[jj] = s0 + s1;
                mloc = fmaxf(mloc, p[jj]);
            }
            float corr = __expf(mrun - mloc);
            mrun = mloc;
            lsum *= corr;
            #pragma unroll
            for (int d = 0; d < 64; d++) o[d] *= corr;
            #pragma unroll
            for (int jj = 0; jj < 16; jj++) {
                p[jj] = __expf(p[jj] - mrun);
                lsum += p[jj];
            }
            #pragma unroll
            for (int jj = 0; jj < 16; jj++) {
                const float* vr = &sV[c * 16 + jj][0];
                float pj = p[jj];
                #pragma unroll
                for (int d = 0; d < 64; d += 4) {
                    float4 vv = *(const float4*)(vr + d);
                    o[d + 0] = fmaf(pj, vv.x, o[d + 0]);
                    o[d + 1] = fmaf(pj, vv.y, o[d + 1]);
                    o[d + 2] = fmaf(pj, vv.z, o[d + 2]);
                    o[d + 3] = fmaf(pj, vv.w, o[d + 3]);
                }
            }
        }
    }

    float inv = 1.0f / lsum;
    float* op = g_attn + hb + (size_t)qrow * EMBED;
    #pragma unroll
    for (int d = 0; d < 64; d += 4) {
        float4 r4 = { o[d] * inv, o[d + 1] * inv, o[d + 2] * inv, o[d + 3] * inv };
        *(float4*)(op + d) = r4;
    }
}

// ============================================================
// Kernel 3: output projection  C[8192][1024] = g_attn @ Wo^T + bo
// BM=BN=128, BK=8, 256 threads, 8x8 micro-tile.
// grid: (EMBED/128, ROWS/128) = (8, 64)
// ============================================================
__global__ __launch_bounds__(256, 2)
void out_gemm(const float* __restrict__ W,   // Wo [1024][1024], row = out col
              const float* __restrict__ bias,
              float* __restrict__ C) {
    __shared__ float sA[8][132];
    __shared__ float sB[8][132];

    const int t = threadIdx.x;
    const int tx = t & 15;
    const int ty = t >> 4;
    const int rowBase = blockIdx.y * 128;
    const int colBase = blockIdx.x * 128;

    float acc[8][8];
    #pragma unroll
    for (int i = 0; i < 8; i++)
        #pragma unroll
        for (int j = 0; j < 8; j++) acc[i][j] = 0.f;

    const int lrow = t >> 1;        // 0..127
    const int lk   = (t & 1) * 4;   // 0 or 4

    const float* Ap = g_attn + (size_t)(rowBase + lrow) * EMBED + lk;
    const float* Bp = W      + (size_t)(colBase + lrow) * EMBED + lk;

    for (int k0 = 0; k0 < EMBED; k0 += 8) {
        float4 av = *(const float4*)(Ap + k0);
        float4 bv = *(const float4*)(Bp + k0);
        __syncthreads();
        sA[lk + 0][lrow] = av.x; sA[lk + 1][lrow] = av.y;
        sA[lk + 2][lrow] = av.z; sA[lk + 3][lrow] = av.w;
        sB[lk + 0][lrow] = bv.x; sB[lk + 1][lrow] = bv.y;
        sB[lk + 2][lrow] = bv.z; sB[lk + 3][lrow] = bv.w;
        __syncthreads();

        #pragma unroll
        for (int k = 0; k < 8; k++) {
            float4 a0 = *(const float4*)&sA[k][ty * 8];
            float4 a1 = *(const float4*)&sA[k][ty * 8 + 4];
            float4 b0 = *(const float4*)&sB[k][tx * 8];
            float4 b1 = *(const float4*)&sB[k][tx * 8 + 4];
            float a[8] = {a0.x, a0.y, a0.z, a0.w, a1.x, a1.y, a1.z, a1.w};
            float b[8] = {b0.x, b0.y, b0.z, b0.w, b1.x, b1.y, b1.z, b1.w};
            #pragma unroll
            for (int i = 0; i < 8; i++)
                #pragma unroll
                for (int j = 0; j < 8; j++)
                    acc[i][j] = fmaf(a[i], b[j], acc[i][j]);
        }
    }

    #pragma unroll
    for (int i = 0; i < 8; i++) {
        int r = rowBase + ty * 8 + i;
        #pragma unroll
        for (int j = 0; j < 8; j += 4) {
            int cidx = colBase + tx * 8 + j;
            float4 bb = *(const float4*)&bias[cidx];
            float4 res = { acc[i][j + 0] + bb.x, acc[i][j + 1] + bb.y,
                           acc[i][j + 2] + bb.z, acc[i][j + 3] + bb.w };
            *(float4*)&C[(size_t)r * EMBED + cidx] = res;
        }
    }
}

// ============================================================
extern "C" void kernel_launch(void* const* d_in, const int* in_sizes, int n_in,
                              void* d_out, int out_size) {
    const float* values = (const float*)d_in[0];
    const float* keys   = (const float*)d_in[1];
    const float* query  = (const float*)d_in[2];
    const float* Wv     = (const float*)d_in[3];
    const float* Wk     = (const float*)d_in[4];
    const float* Wq     = (const float*)d_in[5];
    const float* Wo     = (const float*)d_in[6];
    const float* bo     = (const float*)d_in[7];
    float* out = (float*)d_out;

    // 1) projections: rows = N*L*H = 131072, 32 rows/block
    proj_kernel<<<dim3(131072 / 32, 3), 256>>>(query, keys, values, Wq, Wk, Wv);

    // 2) flash attention
    attn_kernel<<<dim3(SEQ / 128, HEADS, NBATCH), 128>>>();

    // 3) output projection + bias
    out_gemm<<<dim3(EMBED / 128, (NBATCH * SEQ) / 128), 256>>>(Wo, bo, out);
}

// round 3
// speedup vs baseline: 3.7472x; 3.7472x over previous
#include <cuda_runtime.h>
#include <cstdint>
#include <math.h>

#define EMBED  1024
#define HEADS  16
#define HDIM   64
#define NBATCH 4
#define SEQ    2048

// ---- scratch (static __device__ globals; no allocation) ----
__device__ float g_q[(size_t)NBATCH * SEQ * EMBED];
__device__ float g_k[(size_t)NBATCH * SEQ * EMBED];
__device__ float g_v[(size_t)NBATCH * SEQ * EMBED];
__device__ float g_attn[(size_t)NBATCH * SEQ * EMBED];

// ============================================================
// helpers
// ============================================================
__device__ __forceinline__ uint32_t f2tf32(float f) {
    uint32_t u;
    asm("cvt.rna.tf32.f32 %0, %1;" : "=r"(u) : "f"(f));
    return u;
}

__device__ __forceinline__ void mma_tf32(float c[4],
                                         uint32_t a0, uint32_t a1, uint32_t a2, uint32_t a3,
                                         uint32_t b0, uint32_t b1) {
    asm volatile(
        "mma.sync.aligned.m16n8k8.row.col.f32.tf32.tf32.f32 "
        "{%0,%1,%2,%3}, {%4,%5,%6,%7}, {%8,%9}, {%0,%1,%2,%3};"
        : "+f"(c[0]), "+f"(c[1]), "+f"(c[2]), "+f"(c[3])
        : "r"(a0), "r"(a1), "r"(a2), "r"(a3), "r"(b0), "r"(b1));
}

// ============================================================
// Kernel 1: per-head-dim projections
// ============================================================
__global__ void proj_kernel(const float* __restrict__ xq,
                            const float* __restrict__ xk,
                            const float* __restrict__ xv,
                            const float* __restrict__ Wq,
                            const float* __restrict__ Wk,
                            const float* __restrict__ Wv) {
    __shared__ float sW[64][68];
    __shared__ float sX[32][68];

    const float* x;
    const float* W;
    float* o;
    switch (blockIdx.y) {
        case 0:  x = xq; W = Wq; o = g_q; break;
        case 1:  x = xk; W = Wk; o = g_k; break;
        default: x = xv; W = Wv; o = g_v; break;
    }

    const int t = threadIdx.x;
    const int row0 = blockIdx.x * 32;

    #pragma unroll
    for (int i = t; i < 1024; i += 256) {
        int e = i >> 4;
        int d = (i & 15) * 4;
        *(float4*)&sW[e][d] = *(const float4*)&W[e * 64 + d];
    }
    #pragma unroll
    for (int i = t; i < 512; i += 256) {
        int r = i >> 4;
        int d = (i & 15) * 4;
        *(float4*)&sX[r][d] = *(const float4*)&x[(size_t)(row0 + r) * 64 + d];
    }
    __syncthreads();

    #pragma unroll
    for (int j = 0; j < 8; j++) {
        int idx = t + j * 256;
        int r = idx >> 6;
        int e = idx & 63;
        float acc = 0.f;
        #pragma unroll
        for (int d = 0; d < 64; d += 4) {
            float4 xx = *(const float4*)&sX[r][d];
            float4 ww = *(const float4*)&sW[e][d];
            acc = fmaf(xx.x, ww.x, acc);
            acc = fmaf(xx.y, ww.y, acc);
            acc = fmaf(xx.z, ww.z, acc);
            acc = fmaf(xx.w, ww.w, acc);
        }
        o[(size_t)(row0 + r) * 64 + e] = acc;
    }
}

// ============================================================
// Kernel 2: flash attention on mma.sync tf32 (HMMA path)
// CTA = 128 q rows of one (n,h), 256 threads (8 warps).
// warp w owns q rows [128*bx + 16w, +16).
// ============================================================
#define PAD_K 68
#define PAD_V 132
#define PAD_P 132
#define SK_OFF 0
#define SV_OFF (128 * PAD_K * 4)                 // 34816
#define SP_OFF (SV_OFF + 64 * PAD_V * 4)         // 34816+33792=68608
#define SM_TOTAL_ATTN (SP_OFF + 128 * PAD_P * 4) // 136192

__global__ __launch_bounds__(256, 1)
void attn_mma_kernel() {
    extern __shared__ char smem[];
    uint32_t* sK = (uint32_t*)(smem + SK_OFF);  // [kv][d]   tf32, stride PAD_K
    uint32_t* sV = (uint32_t*)(smem + SV_OFF);  // [d][kv]   tf32, stride PAD_V
    uint32_t* sP = (uint32_t*)(smem + SP_OFF);  // [q][kv]   tf32, stride PAD_P

    const int tid  = threadIdx.x;
    const int w    = tid >> 5;
    const int lane = tid & 31;
    const int g    = lane >> 2;   // groupID 0..7
    const int t    = lane & 3;    // threadID in group

    const int nb = blockIdx.z;
    const int h  = blockIdx.y;
    const size_t hb = (size_t)nb * SEQ * EMBED + (size_t)h * HDIM;
    const int q0 = blockIdx.x * 128;
    const int lr0 = w * 16 + g;        // CTA-local q row for c0/c1
    const int r0 = q0 + lr0;           // global q row
    const int r1 = r0 + 8;

    // ---- Q fragments in registers for entire kv loop (scaled 1/32, tf32) ----
    uint32_t qa[8][4];
    {
        const float* Qp = g_q + hb;
        const float* q0p = Qp + (size_t)r0 * EMBED;
        const float* q1p = Qp + (size_t)r1 * EMBED;
        #pragma unroll
        for (int k = 0; k < 8; k++) {
            qa[k][0] = f2tf32(q0p[8 * k + t]     * 0.03125f);
            qa[k][1] = f2tf32(q1p[8 * k + t]     * 0.03125f);
            qa[k][2] = f2tf32(q0p[8 * k + t + 4] * 0.03125f);
            qa[k][3] = f2tf32(q1p[8 * k + t + 4] * 0.03125f);
        }
    }

    float acc[8][4];
    #pragma unroll
    for (int i = 0; i < 8; i++)
        #pragma unroll
        for (int j = 0; j < 4; j++) acc[i][j] = 0.f;
    float rs0 = 0.f, rs1 = 0.f;

    for (int kt = 0; kt < SEQ / 128; kt++) {
        __syncthreads();   // previous tile fully consumed

        // ---- stage K tile [128][64] -> sK[kv][d] (tf32) ----
        {
            const float* kp = g_k + hb + (size_t)(kt * 128) * EMBED;
            #pragma unroll
            for (int i = 0; i < 8; i++) {
                int idx = tid + i * 256;       // 0..2047 float4 slots
                int r  = idx >> 4;
                int c4 = idx & 15;
                float4 v = *(const float4*)(kp + (size_t)r * EMBED + c4 * 4);
                uint32_t* dst = &sK[r * PAD_K + c4 * 4];
                dst[0] = f2tf32(v.x); dst[1] = f2tf32(v.y);
                dst[2] = f2tf32(v.z); dst[3] = f2tf32(v.w);
            }
        }
        // ---- stage V tile transposed -> sV[d][kv] (tf32) ----
        {
            const float* vp = g_v + hb + (size_t)(kt * 128) * EMBED;
            #pragma unroll
            for (int i = 0; i < 8; i++) {
                int idx = tid + i * 256;
                int r  = idx >> 4;
                int c4 = idx & 15;
                float4 v = *(const float4*)(vp + (size_t)r * EMBED + c4 * 4);
                sV[(c4 * 4 + 0) * PAD_V + r] = f2tf32(v.x);
                sV[(c4 * 4 + 1) * PAD_V + r] = f2tf32(v.y);
                sV[(c4 * 4 + 2) * PAD_V + r] = f2tf32(v.z);
                sV[(c4 * 4 + 3) * PAD_V + r] = f2tf32(v.w);
            }
        }
        __syncthreads();

        // ---- S = Q K^T, exp in regs, store P (warp-private rows) ----
        #pragma unroll
        for (int nt = 0; nt < 16; nt++) {
            const int n0 = nt * 8;
            float c[4] = {0.f, 0.f, 0.f, 0.f};
            #pragma unroll
            for (int k = 0; k < 8; k++) {
                uint32_t b0 = sK[(n0 + g) * PAD_K + 8 * k + t];
                uint32_t b1 = sK[(n0 + g) * PAD_K + 8 * k + t + 4];
                mma_tf32(c, qa[k][0], qa[k][1], qa[k][2], qa[k][3], b0, b1);
            }
            float p0 = __expf(c[0]);
            float p1 = __expf(c[1]);
            float p2 = __expf(c[2]);
            float p3 = __expf(c[3]);
            rs0 += p0 + p1;
            rs1 += p2 + p3;
            uint32_t* pp0 = &sP[lr0 * PAD_P + n0 + 2 * t];
            pp0[0] = f2tf32(p0); pp0[1] = f2tf32(p1);
            uint32_t* pp1 = &sP[(lr0 + 8) * PAD_P + n0 + 2 * t];
            pp1[0] = f2tf32(p2); pp1[1] = f2tf32(p3);
        }
        // no sync: each warp reads back only its own sP rows

        // ---- O += P V ----
        #pragma unroll
        for (int k = 0; k < 16; k++) {
            uint32_t a0 = sP[lr0 * PAD_P       + 8 * k + t];
            uint32_t a1 = sP[(lr0 + 8) * PAD_P + 8 * k + t];
            uint32_t a2 = sP[lr0 * PAD_P       + 8 * k + t + 4];
            uint32_t a3 = sP[(lr0 + 8) * PAD_P + 8 * k + t + 4];
            #pragma unroll
            for (int nt = 0; nt < 8; nt++) {
                uint32_t b0 = sV[(nt * 8 + g) * PAD_V + 8 * k + t];
                uint32_t b1 = sV[(nt * 8 + g) * PAD_V + 8 * k + t + 4];
                mma_tf32(acc[nt], a0, a1, a2, a3, b0, b1);
            }
        }
    }

    // ---- reduce row sums across quad, normalize, write out ----
    rs0 += __shfl_xor_sync(0xffffffffu, rs0, 1);
    rs0 += __shfl_xor_sync(0xffffffffu, rs0, 2);
    rs1 += __shfl_xor_sync(0xffffffffu, rs1, 1);
    rs1 += __shfl_xor_sync(0xffffffffu, rs1, 2);
    const float inv0 = 1.0f / rs0;
    const float inv1 = 1.0f / rs1;

    float* op0 = g_attn + hb + (size_t)r0 * EMBED;
    float* op1 = g_attn + hb + (size_t)r1 * EMBED;
    #pragma unroll
    for (int nt = 0; nt < 8; nt++) {
        int col = nt * 8 + 2 * t;
        float2 v0 = { acc[nt][0] * inv0, acc[nt][1] * inv0 };
        float2 v1 = { acc[nt][2] * inv1, acc[nt][3] * inv1 };
        *(float2*)(op0 + col) = v0;
        *(float2*)(op1 + col) = v1;
    }
}

// ============================================================
// Kernel 3: output projection  C[8192][1024] = g_attn @ Wo^T + bo
// ============================================================
__global__ __launch_bounds__(256, 2)
void out_gemm(const float* __restrict__ W,
              const float* __restrict__ bias,
              float* __restrict__ C) {
    __shared__ float sA[8][132];
    __shared__ float sB[8][132];

    const int t = threadIdx.x;
    const int tx = t & 15;
    const int ty = t >> 4;
    const int rowBase = blockIdx.y * 128;
    const int colBase = blockIdx.x * 128;

    float acc[8][8];
    #pragma unroll
    for (int i = 0; i < 8; i++)
        #pragma unroll
        for (int j = 0; j < 8; j++) acc[i][j] = 0.f;

    const int lrow = t >> 1;
    const int lk   = (t & 1) * 4;

    const float* Ap = g_attn + (size_t)(rowBase + lrow) * EMBED + lk;
    const float* Bp = W      + (size_t)(colBase + lrow) * EMBED + lk;

    for (int k0 = 0; k0 < EMBED; k0 += 8) {
        float4 av = *(const float4*)(Ap + k0);
        float4 bv = *(const float4*)(Bp + k0);
        __syncthreads();
        sA[lk + 0][lrow] = av.x; sA[lk + 1][lrow] = av.y;
        sA[lk + 2][lrow] = av.z; sA[lk + 3][lrow] = av.w;
        sB[lk + 0][lrow] = bv.x; sB[lk + 1][lrow] = bv.y;
        sB[lk + 2][lrow] = bv.z; sB[lk + 3][lrow] = bv.w;
        __syncthreads();

        #pragma unroll
        for (int k = 0; k < 8; k++) {
            float4 a0 = *(const float4*)&sA[k][ty * 8];
            float4 a1 = *(const float4*)&sA[k][ty * 8 + 4];
            float4 b0 = *(const float4*)&sB[k][tx * 8];
            float4 b1 = *(const float4*)&sB[k][tx * 8 + 4];
            float a[8] = {a0.x, a0.y, a0.z, a0.w, a1.x, a1.y, a1.z, a1.w};
            float b[8] = {b0.x, b0.y, b0.z, b0.w, b1.x, b1.y, b1.z, b1.w};
            #pragma unroll
            for (int i = 0; i < 8; i++)
                #pragma unroll
                for (int j = 0; j < 8; j++)
                    acc[i][j] = fmaf(a[i], b[j], acc[i][j]);
        }
    }

    #pragma unroll
    for (int i = 0; i < 8; i++) {
        int r = rowBase + ty * 8 + i;
        #pragma unroll
        for (int j = 0; j < 8; j += 4) {
            int cidx = colBase + tx * 8 + j;
            float4 bb = *(const float4*)&bias[cidx];
            float4 res = { acc[i][j + 0] + bb.x, acc[i][j + 1] + bb.y,
                           acc[i][j + 2] + bb.z, acc[i][j + 3] + bb.w };
            *(float4*)&C[(size_t)r * EMBED + cidx] = res;
        }
    }
}

// ============================================================
extern "C" void kernel_launch(void* const* d_in, const int* in_sizes, int n_in,
                              void* d_out, int out_size) {
    const float* values = (const float*)d_in[0];
    const float* keys   = (const float*)d_in[1];
    const float* query  = (const float*)d_in[2];
    const float* Wv     = (const float*)d_in[3];
    const float* Wk     = (const float*)d_in[4];
    const float* Wq     = (const float*)d_in[5];
    const float* Wo     = (const float*)d_in[6];
    const float* bo     = (const float*)d_in[7];
    float* out = (float*)d_out;

    // 1) projections
    proj_kernel<<<dim3(131072 / 32, 3), 256>>>(query, keys, values, Wq, Wk, Wv);

    // 2) flash attention (mma.sync tf32)
    static int smem_set = 0;
    if (!smem_set) {
        cudaFuncSetAttribute(attn_mma_kernel,
                             cudaFuncAttributeMaxDynamicSharedMemorySize, SM_TOTAL_ATTN);
        smem_set = 1;
    }
    attn_mma_kernel<<<dim3(SEQ / 128, HEADS, NBATCH), 256, SM_TOTAL_ATTN>>>();

    // 3) output projection + bias
    out_gemm<<<dim3(EMBED / 128, (NBATCH * SEQ) / 128), 256>>>(Wo, bo, out);
}

// round 4
// speedup vs baseline: 4.9651x; 1.3250x over previous
#include <cuda_runtime.h>
#include <cstdint>
#include <math.h>

#define EMBED  1024
#define HEADS  16
#define HDIM   64
#define NBATCH 4
#define SEQ    2048

// ---- scratch (static __device__ globals; no allocation) ----
__device__ float g_q[(size_t)NBATCH * SEQ * EMBED];
__device__ float g_k[(size_t)NBATCH * SEQ * EMBED];
__device__ float g_v[(size_t)NBATCH * SEQ * EMBED];
__device__ float g_attn[(size_t)NBATCH * SEQ * EMBED];

// ============================================================
// helpers
// ============================================================
__device__ __forceinline__ uint32_t f2tf32(float f) {
    uint32_t u;
    asm("cvt.rna.tf32.f32 %0, %1;" : "=r"(u) : "f"(f));
    return u;
}

__device__ __forceinline__ void mma_tf32(float c[4],
                                         uint32_t a0, uint32_t a1, uint32_t a2, uint32_t a3,
                                         uint32_t b0, uint32_t b1) {
    asm volatile(
        "mma.sync.aligned.m16n8k8.row.col.f32.tf32.tf32.f32 "
        "{%0,%1,%2,%3}, {%4,%5,%6,%7}, {%8,%9}, {%0,%1,%2,%3};"
        : "+f"(c[0]), "+f"(c[1]), "+f"(c[2]), "+f"(c[3])
        : "r"(a0), "r"(a1), "r"(a2), "r"(a3), "r"(b0), "r"(b1));
}

// ============================================================
// Kernel 1: per-head-dim projections on tf32 MMA.
// rows = N*L*H = 131072, 128 rows/CTA, 256 threads (8 warps).
// warp w: rows [16w, 16w+16). grid (1024, 3).
// Softmax scale 1/32 folded into Wq (blockIdx.y == 0).
// ============================================================
#define PPAD 68
#define PROJ_SMEM ((128 + 64) * PPAD * 4)

__global__ __launch_bounds__(256)
void proj_mma_kernel(const float* __restrict__ xq,
                     const float* __restrict__ xk,
                     const float* __restrict__ xv,
                     const float* __restrict__ Wq,
                     const float* __restrict__ Wk,
                     const float* __restrict__ Wv) {
    extern __shared__ uint32_t psm[];
    uint32_t* sX = psm;                 // [128][PPAD] tf32
    uint32_t* sW = psm + 128 * PPAD;    // [64][PPAD]  tf32

    const float* x;
    const float* W;
    float* o;
    float wscale;
    switch (blockIdx.y) {
        case 0:  x = xq; W = Wq; o = g_q; wscale = 0.03125f; break;
        case 1:  x = xk; W = Wk; o = g_k; wscale = 1.0f;     break;
        default: x = xv; W = Wv; o = g_v; wscale = 1.0f;     break;
    }

    const int tid = threadIdx.x;
    const int row0 = blockIdx.x * 128;

    // stage W [64][64] -> tf32
    #pragma unroll
    for (int i = 0; i < 4; i++) {
        int idx = tid + i * 256;        // 0..1023
        int r  = idx >> 4;
        int c4 = (idx & 15) * 4;
        float4 v = *(const float4*)&W[r * 64 + c4];
        uint32_t* dst = &sW[r * PPAD + c4];
        dst[0] = f2tf32(v.x * wscale); dst[1] = f2tf32(v.y * wscale);
        dst[2] = f2tf32(v.z * wscale); dst[3] = f2tf32(v.w * wscale);
    }
    // stage X [128][64] -> tf32
    #pragma unroll
    for (int i = 0; i < 8; i++) {
        int idx = tid + i * 256;        // 0..2047
        int r  = idx >> 4;
        int c4 = (idx & 15) * 4;
        float4 v = *(const float4*)&x[(size_t)(row0 + r) * 64 + c4];
        uint32_t* dst = &sX[r * PPAD + c4];
        dst[0] = f2tf32(v.x); dst[1] = f2tf32(v.y);
        dst[2] = f2tf32(v.z); dst[3] = f2tf32(v.w);
    }
    __syncthreads();

    const int w    = tid >> 5;
    const int lane = tid & 31;
    const int g    = lane >> 2;
    const int t    = lane & 3;

    float acc[8][4];
    #pragma unroll
    for (int n = 0; n < 8; n++)
        #pragma unroll
        for (int j = 0; j < 4; j++) acc[n][j] = 0.f;

    const uint32_t* ax = &sX[(w * 16 + g) * PPAD];
    #pragma unroll
    for (int k = 0; k < 8; k++) {
        uint32_t a0 = ax[8 * k + t];
        uint32_t a1 = ax[8 * PPAD + 8 * k + t];
        uint32_t a2 = ax[8 * k + t + 4];
        uint32_t a3 = ax[8 * PPAD + 8 * k + t + 4];
        #pragma unroll
        for (int n = 0; n < 8; n++) {
            uint32_t b0 = sW[(n * 8 + g) * PPAD + 8 * k + t];
            uint32_t b1 = sW[(n * 8 + g) * PPAD + 8 * k + t + 4];
            mma_tf32(acc[n], a0, a1, a2, a3, b0, b1);
        }
    }

    float* o0 = o + (size_t)(row0 + w * 16 + g) * 64;
    float* o1 = o0 + 8 * 64;
    #pragma unroll
    for (int n = 0; n < 8; n++) {
        int col = n * 8 + 2 * t;
        *(float2*)(o0 + col) = make_float2(acc[n][0], acc[n][1]);
        *(float2*)(o1 + col) = make_float2(acc[n][2], acc[n][3]);
    }
}

// ============================================================
// Kernel 2: flash attention on mma.sync tf32 (scale pre-folded into Wq)
// CTA = 128 q rows of one (n,h), 256 threads (8 warps).
// ============================================================
#define PAD_K 68
#define PAD_V 132
#define PAD_P 132
#define SK_OFF 0
#define SV_OFF (128 * PAD_K * 4)
#define SP_OFF (SV_OFF + 64 * PAD_V * 4)
#define SM_TOTAL_ATTN (SP_OFF + 128 * PAD_P * 4)

__global__ __launch_bounds__(256, 1)
void attn_mma_kernel() {
    extern __shared__ char smem[];
    uint32_t* sK = (uint32_t*)(smem + SK_OFF);  // [kv][d]   tf32
    uint32_t* sV = (uint32_t*)(smem + SV_OFF);  // [d][kv]   tf32
    uint32_t* sP = (uint32_t*)(smem + SP_OFF);  // [q][kv]   tf32

    const int tid  = threadIdx.x;
    const int w    = tid >> 5;
    const int lane = tid & 31;
    const int g    = lane >> 2;
    const int t    = lane & 3;

    const int nb = blockIdx.z;
    const int h  = blockIdx.y;
    const size_t hb = (size_t)nb * SEQ * EMBED + (size_t)h * HDIM;
    const int q0 = blockIdx.x * 128;
    const int lr0 = w * 16 + g;
    const int r0 = q0 + lr0;
    const int r1 = r0 + 8;

    // ---- Q fragments in registers for entire kv loop ----
    uint32_t qa[8][4];
    {
        const float* q0p = g_q + hb + (size_t)r0 * EMBED;
        const float* q1p = g_q + hb + (size_t)r1 * EMBED;
        #pragma unroll
        for (int k = 0; k < 8; k++) {
            qa[k][0] = f2tf32(q0p[8 * k + t]);
            qa[k][1] = f2tf32(q1p[8 * k + t]);
            qa[k][2] = f2tf32(q0p[8 * k + t + 4]);
            qa[k][3] = f2tf32(q1p[8 * k + t + 4]);
        }
    }

    float acc[8][4];
    #pragma unroll
    for (int i = 0; i < 8; i++)
        #pragma unroll
        for (int j = 0; j < 4; j++) acc[i][j] = 0.f;
    float rs0 = 0.f, rs1 = 0.f;

    for (int kt = 0; kt < SEQ / 128; kt++) {
        __syncthreads();

        // ---- stage K tile [128][64] -> sK[kv][d] (tf32) ----
        {
            const float* kp = g_k + hb + (size_t)(kt * 128) * EMBED;
            #pragma unroll
            for (int i = 0; i < 8; i++) {
                int idx = tid + i * 256;
                int r  = idx >> 4;
                int c4 = idx & 15;
                float4 v = *(const float4*)(kp + (size_t)r * EMBED + c4 * 4);
                uint32_t* dst = &sK[r * PAD_K + c4 * 4];
                dst[0] = f2tf32(v.x); dst[1] = f2tf32(v.y);
                dst[2] = f2tf32(v.z); dst[3] = f2tf32(v.w);
            }
        }
        // ---- stage V tile transposed -> sV[d][kv] (tf32) ----
        {
            const float* vp = g_v + hb + (size_t)(kt * 128) * EMBED;
            #pragma unroll
            for (int i = 0; i < 8; i++) {
                int idx = tid + i * 256;
                int r  = idx >> 4;
                int c4 = idx & 15;
                float4 v = *(const float4*)(vp + (size_t)r * EMBED + c4 * 4);
                sV[(c4 * 4 + 0) * PAD_V + r] = f2tf32(v.x);
                sV[(c4 * 4 + 1) * PAD_V + r] = f2tf32(v.y);
                sV[(c4 * 4 + 2) * PAD_V + r] = f2tf32(v.z);
                sV[(c4 * 4 + 3) * PAD_V + r] = f2tf32(v.w);
            }
        }
        __syncthreads();

        // ---- S = Q K^T, exp in regs, store P (warp-private rows) ----
        #pragma unroll
        for (int nt = 0; nt < 16; nt++) {
            const int n0 = nt * 8;
            float c[4] = {0.f, 0.f, 0.f, 0.f};
            #pragma unroll
            for (int k = 0; k < 8; k++) {
                uint32_t b0 = sK[(n0 + g) * PAD_K + 8 * k + t];
                uint32_t b1 = sK[(n0 + g) * PAD_K + 8 * k + t + 4];
                mma_tf32(c, qa[k][0], qa[k][1], qa[k][2], qa[k][3], b0, b1);
            }
            float p0 = __expf(c[0]);
            float p1 = __expf(c[1]);
            float p2 = __expf(c[2]);
            float p3 = __expf(c[3]);
            rs0 += p0 + p1;
            rs1 += p2 + p3;
            uint32_t* pp0 = &sP[lr0 * PAD_P + n0 + 2 * t];
            pp0[0] = f2tf32(p0); pp0[1] = f2tf32(p1);
            uint32_t* pp1 = &sP[(lr0 + 8) * PAD_P + n0 + 2 * t];
            pp1[0] = f2tf32(p2); pp1[1] = f2tf32(p3);
        }
        // no sync: each warp reads back only its own sP rows

        // ---- O += P V ----
        #pragma unroll
        for (int k = 0; k < 16; k++) {
            uint32_t a0 = sP[lr0 * PAD_P       + 8 * k + t];
            uint32_t a1 = sP[(lr0 + 8) * PAD_P + 8 * k + t];
            uint32_t a2 = sP[lr0 * PAD_P       + 8 * k + t + 4];
            uint32_t a3 = sP[(lr0 + 8) * PAD_P + 8 * k + t + 4];
            #pragma unroll
            for (int nt = 0; nt < 8; nt++) {
                uint32_t b0 = sV[(nt * 8 + g) * PAD_V + 8 * k + t];
                uint32_t b1 = sV[(nt * 8 + g) * PAD_V + 8 * k + t + 4];
                mma_tf32(acc[nt], a0, a1, a2, a3, b0, b1);
            }
        }
    }

    rs0 += __shfl_xor_sync(0xffffffffu, rs0, 1);
    rs0 += __shfl_xor_sync(0xffffffffu, rs0, 2);
    rs1 += __shfl_xor_sync(0xffffffffu, rs1, 1);
    rs1 += __shfl_xor_sync(0xffffffffu, rs1, 2);
    const float inv0 = 1.0f / rs0;
    const float inv1 = 1.0f / rs1;

    float* op0 = g_attn + hb + (size_t)r0 * EMBED;
    float* op1 = g_attn + hb + (size_t)r1 * EMBED;
    #pragma unroll
    for (int nt = 0; nt < 8; nt++) {
        int col = nt * 8 + 2 * t;
        *(float2*)(op0 + col) = make_float2(acc[nt][0] * inv0, acc[nt][1] * inv0);
        *(float2*)(op1 + col) = make_float2(acc[nt][2] * inv1, acc[nt][3] * inv1);
    }
}

// ============================================================
// Kernel 3: output projection on tf32 MMA.
// C[8192][1024] = g_attn @ Wo^T + bo.
// BM=BN=128, BK=32; 256 threads, 8 warps (4x2), warp tile 32x64.
// grid (8, 64).
// ============================================================
#define GPAD 36

__global__ __launch_bounds__(256)
void out_gemm_mma(const float* __restrict__ W,
                  const float* __restrict__ bias,
                  float* __restrict__ C) {
    __shared__ uint32_t sA[128 * GPAD];
    __shared__ uint32_t sB[128 * GPAD];

    const int tid  = threadIdx.x;
    const int w    = tid >> 5;
    const int lane = tid & 31;
    const int g    = lane >> 2;
    const int t    = lane & 3;
    const int wm   = w & 3;       // 0..3 (M)
    const int wn   = w >> 2;      // 0..1 (N)

    const int rowBase = blockIdx.y * 128;
    const int colBase = blockIdx.x * 128;

    float acc[2][8][4];
    #pragma unroll
    for (int i = 0; i < 2; i++)
        #pragma unroll
        for (int n = 0; n < 8; n++)
            #pragma unroll
            for (int j = 0; j < 4; j++) acc[i][n][j] = 0.f;

    for (int k0 = 0; k0 < EMBED; k0 += 32) {
        __syncthreads();
        // stage A [128][32], B [128][32] -> tf32
        #pragma unroll
        for (int i = 0; i < 4; i++) {
            int idx = tid + i * 256;      // 0..1023
            int r  = idx >> 3;
            int c4 = (idx & 7) * 4;
            float4 va = *(const float4*)&g_attn[(size_t)(rowBase + r) * EMBED + k0 + c4];
            uint32_t* da = &sA[r * GPAD + c4];
            da[0] = f2tf32(va.x); da[1] = f2tf32(va.y);
            da[2] = f2tf32(va.z); da[3] = f2tf32(va.w);
            float4 vb = *(const float4*)&W[(size_t)(colBase + r) * EMBED + k0 + c4];
            uint32_t* db = &sB[r * GPAD + c4];
            db[0] = f2tf32(vb.x); db[1] = f2tf32(vb.y);
            db[2] = f2tf32(vb.z); db[3] = f2tf32(vb.w);
        }
        __syncthreads();

        #pragma unroll
        for (int kk = 0; kk < 4; kk++) {
            uint32_t a[2][4];
            #pragma unroll
            for (int i0 = 0; i0 < 2; i0++) {
                const uint32_t* ar = &sA[(wm * 32 + i0 * 16 + g) * GPAD];
                a[i0][0] = ar[8 * kk + t];
                a[i0][1] = ar[8 * GPAD + 8 * kk + t];
                a[i0][2] = ar[8 * kk + t + 4];
                a[i0][3] = ar[8 * GPAD + 8 * kk + t + 4];
            }
            #pragma unroll
            for (int n = 0; n < 8; n++) {
                uint32_t b0 = sB[(wn * 64 + n * 8 + g) * GPAD + 8 * kk + t];
                uint32_t b1 = sB[(wn * 64 + n * 8 + g) * GPAD + 8 * kk + t + 4];
                mma_tf32(acc[0][n], a[0][0], a[0][1], a[0][2], a[0][3], b0, b1);
                mma_tf32(acc[1][n], a[1][0], a[1][1], a[1][2], a[1][3], b0, b1);
            }
        }
    }

    // epilogue: add bias, write C
    #pragma unroll
    for (int i0 = 0; i0 < 2; i0++) {
        int row = rowBase + wm * 32 + i0 * 16 + g;
        float* c0 = &C[(size_t)row * EMBED];
        float* c1 = &C[(size_t)(row + 8) * EMBED];
        #pragma unroll
        for (int n = 0; n < 8; n++) {
            int col = colBase + wn * 64 + n * 8 + 2 * t;
            float2 bb = *(const float2*)&bias[col];
            *(float2*)(c0 + col) = make_float2(acc[i0][n][0] + bb.x, acc[i0][n][1] + bb.y);
            *(float2*)(c1 + col) = make_float2(acc[i0][n][2] + bb.x, acc[i0][n][3] + bb.y);
        }
    }
}

// ============================================================
extern "C" void kernel_launch(void* const* d_in, const int* in_sizes, int n_in,
                              void* d_out, int out_size) {
    const float* values = (const float*)d_in[0];
    const float* keys   = (const float*)d_in[1];
    const float* query  = (const float*)d_in[2];
    const float* Wv     = (const float*)d_in[3];
    const float* Wk     = (const float*)d_in[4];
    const float* Wq     = (const float*)d_in[5];
    const float* Wo     = (const float*)d_in[6];
    const float* bo     = (const float*)d_in[7];
    float* out = (float*)d_out;

    static int attr_set = 0;
    if (!attr_set) {
        cudaFuncSetAttribute(attn_mma_kernel,
                             cudaFuncAttributeMaxDynamicSharedMemorySize, SM_TOTAL_ATTN);
        cudaFuncSetAttribute(proj_mma_kernel,
                             cudaFuncAttributeMaxDynamicSharedMemorySize, PROJ_SMEM);
        attr_set = 1;
    }

    // 1) projections (tf32 mma), scale folded into Wq
    proj_mma_kernel<<<dim3(131072 / 128, 3), 256, PROJ_SMEM>>>(query, keys, values, Wq, Wk, Wv);

    // 2) flash attention (mma.sync tf32)
    attn_mma_kernel<<<dim3(SEQ / 128, HEADS, NBATCH), 256, SM_TOTAL_ATTN>>>();

    // 3) output projection + bias (tf32 mma)
    out_gemm_mma<<<dim3(EMBED / 128, (NBATCH * SEQ) / 128), 256>>>(Wo, bo, out);
}

// round 5
// speedup vs baseline: 4.9787x; 1.0027x over previous
#include <cuda_runtime.h>
#include <cstdint>
#include <math.h>

#define EMBED  1024
#define HEADS  16
#define HDIM   64
#define NBATCH 4
#define SEQ    2048

// ---- scratch (static __device__ globals; no allocation) ----
__device__ float g_q[(size_t)NBATCH * SEQ * EMBED];
__device__ float g_k[(size_t)NBATCH * SEQ * EMBED];
__device__ float g_v[(size_t)NBATCH * SEQ * EMBED];
__device__ float g_attn[(size_t)NBATCH * SEQ * EMBED];

// ============================================================
// helpers
// ============================================================
__device__ __forceinline__ uint32_t f2tf32(float f) {
    uint32_t u;
    asm("cvt.rna.tf32.f32 %0, %1;" : "=r"(u) : "f"(f));
    return u;
}

__device__ __forceinline__ void mma_tf32(float c[4],
                                         uint32_t a0, uint32_t a1, uint32_t a2, uint32_t a3,
                                         uint32_t b0, uint32_t b1) {
    asm volatile(
        "mma.sync.aligned.m16n8k8.row.col.f32.tf32.tf32.f32 "
        "{%0,%1,%2,%3}, {%4,%5,%6,%7}, {%8,%9}, {%0,%1,%2,%3};"
        : "+f"(c[0]), "+f"(c[1]), "+f"(c[2]), "+f"(c[3])
        : "r"(a0), "r"(a1), "r"(a2), "r"(a3), "r"(b0), "r"(b1));
}

// ============================================================
// Kernel 1: per-head-dim projections on tf32 MMA.
// rows = N*L*H = 131072, 128 rows/CTA, 256 threads (8 warps).
// warp w: rows [16w, 16w+16). grid (1024, 3).
// Softmax scale 1/32 folded into Wq (blockIdx.y == 0).
// ============================================================
#define PPAD 68
#define PROJ_SMEM ((128 + 64) * PPAD * 4)

__global__ __launch_bounds__(256)
void proj_mma_kernel(const float* __restrict__ xq,
                     const float* __restrict__ xk,
                     const float* __restrict__ xv,
                     const float* __restrict__ Wq,
                     const float* __restrict__ Wk,
                     const float* __restrict__ Wv) {
    extern __shared__ uint32_t psm[];
    uint32_t* sX = psm;                 // [128][PPAD] tf32
    uint32_t* sW = psm + 128 * PPAD;    // [64][PPAD]  tf32

    const float* x;
    const float* W;
    float* o;
    float wscale;
    switch (blockIdx.y) {
        case 0:  x = xq; W = Wq; o = g_q; wscale = 0.03125f; break;
        case 1:  x = xk; W = Wk; o = g_k; wscale = 1.0f;     break;
        default: x = xv; W = Wv; o = g_v; wscale = 1.0f;     break;
    }

    const int tid = threadIdx.x;
    const int row0 = blockIdx.x * 128;

    // stage W [64][64] -> tf32
    #pragma unroll
    for (int i = 0; i < 4; i++) {
        int idx = tid + i * 256;        // 0..1023
        int r  = idx >> 4;
        int c4 = (idx & 15) * 4;
        float4 v = *(const float4*)&W[r * 64 + c4];
        uint32_t* dst = &sW[r * PPAD + c4];
        dst[0] = f2tf32(v.x * wscale); dst[1] = f2tf32(v.y * wscale);
        dst[2] = f2tf32(v.z * wscale); dst[3] = f2tf32(v.w * wscale);
    }
    // stage X [128][64] -> tf32
    #pragma unroll
    for (int i = 0; i < 8; i++) {
        int idx = tid + i * 256;        // 0..2047
        int r  = idx >> 4;
        int c4 = (idx & 15) * 4;
        float4 v = *(const float4*)&x[(size_t)(row0 + r) * 64 + c4];
        uint32_t* dst = &sX[r * PPAD + c4];
        dst[0] = f2tf32(v.x); dst[1] = f2tf32(v.y);
        dst[2] = f2tf32(v.z); dst[3] = f2tf32(v.w);
    }
    __syncthreads();

    const int w    = tid >> 5;
    const int lane = tid & 31;
    const int g    = lane >> 2;
    const int t    = lane & 3;

    float acc[8][4];
    #pragma unroll
    for (int n = 0; n < 8; n++)
        #pragma unroll
        for (int j = 0; j < 4; j++) acc[n][j] = 0.f;

    const uint32_t* ax = &sX[(w * 16 + g) * PPAD];
    #pragma unroll
    for (int k = 0; k < 8; k++) {
        uint32_t a0 = ax[8 * k + t];
        uint32_t a1 = ax[8 * PPAD + 8 * k + t];
        uint32_t a2 = ax[8 * k + t + 4];
        uint32_t a3 = ax[8 * PPAD + 8 * k + t + 4];
        #pragma unroll
        for (int n = 0; n < 8; n++) {
            uint32_t b0 = sW[(n * 8 + g) * PPAD + 8 * k + t];
            uint32_t b1 = sW[(n * 8 + g) * PPAD + 8 * k + t + 4];
            mma_tf32(acc[n], a0, a1, a2, a3, b0, b1);
        }
    }

    float* o0 = o + (size_t)(row0 + w * 16 + g) * 64;
    float* o1 = o0 + 8 * 64;
    #pragma unroll
    for (int n = 0; n < 8; n++) {
        int col = n * 8 + 2 * t;
        *(float2*)(o0 + col) = make_float2(acc[n][0], acc[n][1]);
        *(float2*)(o1 + col) = make_float2(acc[n][2], acc[n][3]);
    }
}

// ============================================================
// Kernel 2: flash attention on mma.sync tf32 (scale pre-folded into Wq)
// CTA = 128 q rows of one (n,h), 256 threads (8 warps).
// ============================================================
#define PAD_K 68
#define PAD_V 132
#define PAD_P 132
#define SK_OFF 0
#define SV_OFF (128 * PAD_K * 4)
#define SP_OFF (SV_OFF + 64 * PAD_V * 4)
#define SM_TOTAL_ATTN (SP_OFF + 128 * PAD_P * 4)

__global__ __launch_bounds__(256, 1)
void attn_mma_kernel() {
    extern __shared__ char smem[];
    uint32_t* sK = (uint32_t*)(smem + SK_OFF);  // [kv][d]   tf32
    uint32_t* sV = (uint32_t*)(smem + SV_OFF);  // [d][kv]   tf32
    uint32_t* sP = (uint32_t*)(smem + SP_OFF);  // [q][kv]   tf32

    const int tid  = threadIdx.x;
    const int w    = tid >> 5;
    const int lane = tid & 31;
    const int g    = lane >> 2;
    const int t    = lane & 3;

    const int nb = blockIdx.z;
    const int h  = blockIdx.y;
    const size_t hb = (size_t)nb * SEQ * EMBED + (size_t)h * HDIM;
    const int q0 = blockIdx.x * 128;
    const int lr0 = w * 16 + g;
    const int r0 = q0 + lr0;
    const int r1 = r0 + 8;

    // ---- Q fragments in registers for entire kv loop ----
    uint32_t qa[8][4];
    {
        const float* q0p = g_q + hb + (size_t)r0 * EMBED;
        const float* q1p = g_q + hb + (size_t)r1 * EMBED;
        #pragma unroll
        for (int k = 0; k < 8; k++) {
            qa[k][0] = f2tf32(q0p[8 * k + t]);
            qa[k][1] = f2tf32(q1p[8 * k + t]);
            qa[k][2] = f2tf32(q0p[8 * k + t + 4]);
            qa[k][3] = f2tf32(q1p[8 * k + t + 4]);
        }
    }

    float acc[8][4];
    #pragma unroll
    for (int i = 0; i < 8; i++)
        #pragma unroll
        for (int j = 0; j < 4; j++) acc[i][j] = 0.f;
    float rs0 = 0.f, rs1 = 0.f;

    for (int kt = 0; kt < SEQ / 128; kt++) {
        __syncthreads();

        // ---- stage K tile [128][64] -> sK[kv][d] (tf32) ----
        {
            const float* kp = g_k + hb + (size_t)(kt * 128) * EMBED;
            #pragma unroll
            for (int i = 0; i < 8; i++) {
                int idx = tid + i * 256;
                int r  = idx >> 4;
                int c4 = idx & 15;
                float4 v = *(const float4*)(kp + (size_t)r * EMBED + c4 * 4);
                uint32_t* dst = &sK[r * PAD_K + c4 * 4];
                dst[0] = f2tf32(v.x); dst[1] = f2tf32(v.y);
                dst[2] = f2tf32(v.z); dst[3] = f2tf32(v.w);
            }
        }
        // ---- stage V tile transposed -> sV[d][kv] (tf32) ----
        {
            const float* vp = g_v + hb + (size_t)(kt * 128) * EMBED;
            #pragma unroll
            for (int i = 0; i < 8; i++) {
                int idx = tid + i * 256;
                int r  = idx >> 4;
                int c4 = idx & 15;
                float4 v = *(const float4*)(vp + (size_t)r * EMBED + c4 * 4);
                sV[(c4 * 4 + 0) * PAD_V + r] = f2tf32(v.x);
                sV[(c4 * 4 + 1) * PAD_V + r] = f2tf32(v.y);
                sV[(c4 * 4 + 2) * PAD_V + r] = f2tf32(v.z);
                sV[(c4 * 4 + 3) * PAD_V + r] = f2tf32(v.w);
            }
        }
        __syncthreads();

        // ---- S = Q K^T, exp in regs, store P (warp-private rows) ----
        #pragma unroll
        for (int nt = 0; nt < 16; nt++) {
            const int n0 = nt * 8;
            float c[4] = {0.f, 0.f, 0.f, 0.f};
            #pragma unroll
            for (int k = 0; k < 8; k++) {
                uint32_t b0 = sK[(n0 + g) * PAD_K + 8 * k + t];
                uint32_t b1 = sK[(n0 + g) * PAD_K + 8 * k + t + 4];
                mma_tf32(c, qa[k][0], qa[k][1], qa[k][2], qa[k][3], b0, b1);
            }
            float p0 = __expf(c[0]);
            float p1 = __expf(c[1]);
            float p2 = __expf(c[2]);
            float p3 = __expf(c[3]);
            rs0 += p0 + p1;
            rs1 += p2 + p3;
            uint32_t* pp0 = &sP[lr0 * PAD_P + n0 + 2 * t];
            pp0[0] = f2tf32(p0); pp0[1] = f2tf32(p1);
            uint32_t* pp1 = &sP[(lr0 + 8) * PAD_P + n0 + 2 * t];
            pp1[0] = f2tf32(p2); pp1[1] = f2tf32(p3);
        }
        // no sync: each warp reads back only its own sP rows

        // ---- O += P V ----
        #pragma unroll
        for (int k = 0; k < 16; k++) {
            uint32_t a0 = sP[lr0 * PAD_P       + 8 * k + t];
            uint32_t a1 = sP[(lr0 + 8) * PAD_P + 8 * k + t];
            uint32_t a2 = sP[lr0 * PAD_P       + 8 * k + t + 4];
            uint32_t a3 = sP[(lr0 + 8) * PAD_P + 8 * k + t + 4];
            #pragma unroll
            for (int nt = 0; nt < 8; nt++) {
                uint32_t b0 = sV[(nt * 8 + g) * PAD_V + 8 * k + t];
                uint32_t b1 = sV[(nt * 8 + g) * PAD_V + 8 * k + t + 4];
                mma_tf32(acc[nt], a0, a1, a2, a3, b0, b1);
            }
        }
    }

    rs0 += __shfl_xor_sync(0xffffffffu, rs0, 1);
    rs0 += __shfl_xor_sync(0xffffffffu, rs0, 2);
    rs1 += __shfl_xor_sync(0xffffffffu, rs1, 1);
    rs1 += __shfl_xor_sync(0xffffffffu, rs1, 2);
    const float inv0 = 1.0f / rs0;
    const float inv1 = 1.0f / rs1;

    float* op0 = g_attn + hb + (size_t)r0 * EMBED;
    float* op1 = g_attn + hb + (size_t)r1 * EMBED;
    #pragma unroll
    for (int nt = 0; nt < 8; nt++) {
        int col = nt * 8 + 2 * t;
        *(float2*)(op0 + col) = make_float2(acc[nt][0] * inv0, acc[nt][1] * inv0);
        *(float2*)(op1 + col) = make_float2(acc[nt][2] * inv1, acc[nt][3] * inv1);
    }
}

// ============================================================
// Kernel 3: output projection on tf32 MMA.
// C[8192][1024] = g_attn @ Wo^T + bo.
// BM=BN=128, BK=32; 256 threads, 8 warps (4x2), warp tile 32x64.
// grid (8, 64).
// ============================================================
#define GPAD 36

__global__ __launch_bounds__(256)
void out_gemm_mma(const float* __restrict__ W,
                  const float* __restrict__ bias,
                  float* __restrict__ C) {
    __shared__ uint32_t sA[128 * GPAD];
    __shared__ uint32_t sB[128 * GPAD];

    const int tid  = threadIdx.x;
    const int w    = tid >> 5;
    const int lane = tid & 31;
    const int g    = lane >> 2;
    const int t    = lane & 3;
    const int wm   = w & 3;       // 0..3 (M)
    const int wn   = w >> 2;      // 0..1 (N)

    const int rowBase = blockIdx.y * 128;
    const int colBase = blockIdx.x * 128;

    float acc[2][8][4];
    #pragma unroll
    for (int i = 0; i < 2; i++)
        #pragma unroll
        for (int n = 0; n < 8; n++)
            #pragma unroll
            for (int j = 0; j < 4; j++) acc[i][n][j] = 0.f;

    for (int k0 = 0; k0 < EMBED; k0 += 32) {
        __syncthreads();
        // stage A [128][32], B [128][32] -> tf32
        #pragma unroll
        for (int i = 0; i < 4; i++) {
            int idx = tid + i * 256;      // 0..1023
            int r  = idx >> 3;
            int c4 = (idx & 7) * 4;
            float4 va = *(const float4*)&g_attn[(size_t)(rowBase + r) * EMBED + k0 + c4];
            uint32_t* da = &sA[r * GPAD + c4];
            da[0] = f2tf32(va.x); da[1] = f2tf32(va.y);
            da[2] = f2tf32(va.z); da[3] = f2tf32(va.w);
            float4 vb = *(const float4*)&W[(size_t)(colBase + r) * EMBED + k0 + c4];
            uint32_t* db = &sB[r * GPAD + c4];
            db[0] = f2tf32(vb.x); db[1] = f2tf32(vb.y);
            db[2] = f2tf32(vb.z); db[3] = f2tf32(vb.w);
        }
        __syncthreads();

        #pragma unroll
        for (int kk = 0; kk < 4; kk++) {
            uint32_t a[2][4];
            #pragma unroll
            for (int i0 = 0; i0 < 2; i0++) {
                const uint32_t* ar = &sA[(wm * 32 + i0 * 16 + g) * GPAD];
                a[i0][0] = ar[8 * kk + t];
                a[i0][1] = ar[8 * GPAD + 8 * kk + t];
                a[i0][2] = ar[8 * kk + t + 4];
                a[i0][3] = ar[8 * GPAD + 8 * kk + t + 4];
            }
            #pragma unroll
            for (int n = 0; n < 8; n++) {
                uint32_t b0 = sB[(wn * 64 + n * 8 + g) * GPAD + 8 * kk + t];
                uint32_t b1 = sB[(wn * 64 + n * 8 + g) * GPAD + 8 * kk + t + 4];
                mma_tf32(acc[0][n], a[0][0], a[0][1], a[0][2], a[0][3], b0, b1);
                mma_tf32(acc[1][n], a[1][0], a[1][1], a[1][2], a[1][3], b0, b1);
            }
        }
    }

    // epilogue: add bias, write C
    #pragma unroll
    for (int i0 = 0; i0 < 2; i0++) {
        int row = rowBase + wm * 32 + i0 * 16 + g;
        float* c0 = &C[(size_t)row * EMBED];
        float* c1 = &C[(size_t)(row + 8) * EMBED];
        #pragma unroll
        for (int n = 0; n < 8; n++) {
            int col = colBase + wn * 64 + n * 8 + 2 * t;
            float2 bb = *(const float2*)&bias[col];
            *(float2*)(c0 + col) = make_float2(acc[i0][n][0] + bb.x, acc[i0][n][1] + bb.y);
            *(float2*)(c1 + col) = make_float2(acc[i0][n][2] + bb.x, acc[i0][n][3] + bb.y);
        }
    }
}

// ============================================================
extern "C" void kernel_launch(void* const* d_in, const int* in_sizes, int n_in,
                              void* d_out, int out_size) {
    const float* values = (const float*)d_in[0];
    const float* keys   = (const float*)d_in[1];
    const float* query  = (const float*)d_in[2];
    const float* Wv     = (const float*)d_in[3];
    const float* Wk     = (const float*)d_in[4];
    const float* Wq     = (const float*)d_in[5];
    const float* Wo     = (const float*)d_in[6];
    const float* bo     = (const float*)d_in[7];
    float* out = (float*)d_out;

    static int attr_set = 0;
    if (!attr_set) {
        cudaFuncSetAttribute(attn_mma_kernel,
                             cudaFuncAttributeMaxDynamicSharedMemorySize, SM_TOTAL_ATTN);
        cudaFuncSetAttribute(proj_mma_kernel,
                             cudaFuncAttributeMaxDynamicSharedMemorySize, PROJ_SMEM);
        attr_set = 1;
    }

    // 1) projections (tf32 mma), scale folded into Wq
    proj_mma_kernel<<<dim3(131072 / 128, 3), 256, PROJ_SMEM>>>(query, keys, values, Wq, Wk, Wv);

    // 2) flash attention (mma.sync tf32)
    attn_mma_kernel<<<dim3(SEQ / 128, HEADS, NBATCH), 256, SM_TOTAL_ATTN>>>();

    // 3) output projection + bias (tf32 mma)
    out_gemm_mma<<<dim3(EMBED / 128, (NBATCH * SEQ) / 128), 256>>>(Wo, bo, out);
}